// round 16
// baseline (speedup 1.0000x reference)
#include <cuda_runtime.h>
#include <math.h>

// ---------------- problem constants ----------------
#define BB 256
#define NN 32
#define HH 256
#define FF 7
#define TT 496
#define RR 8                 // batch rows per 4-CTA cluster
#define NCLUST (BB / RR)
#define NCTA (NCLUST * 4)    // 128 CTAs
#define NT 512
#define HPAD 260             // floats per 32-k block of h (256 + 4 pad)
#define HBUF (8 * HPAD)      // 2080 floats per h buffer
#define EPSF 1.1920929e-07f

typedef unsigned long long ull;

// ---------------- device scratch ----------------
// node weights: [q][kp(32)][col(64)][oct(8)][gate(4)]  (k = oct*32 + kp)
__device__ float g_WcN[4 * 32 * 64 * 8 * 4];
// graph weights combined: [q][kp(64)][col(64)][oct(8)][gate(4)]
//   oct: m = oct>>2 (0=Wih_g, 1=Whh_g), kq = oct&3, k = kq*64 + kp; gate3 = 0
__device__ float g_Wg2[4 * 64 * 64 * 8 * 4];
__device__ float g_bv4[4 * 256];         // node combined bias [q][col*4+g]
__device__ float g_bgi4[4 * 256];
__device__ float g_bgh4[4 * 256];
__device__ float g_PQi4[4 * FF * 256];   // one-hot gathers [q][f][col*4+g], g3=0
__device__ float g_PQj4[4 * FF * 256];
__device__ float g_Ws1T[HH * 64];        // Ws1 transposed [k][u]
__device__ int   g_idx[BB * NN];
__device__ int   g_rd[TT];
__device__ int   g_cd[TT];

// output layout (float32): [x 57344][adj 262144][batch 8192]
#define OUT_X 0
#define OUT_ADJ 57344
#define OUT_BATCH 319488

// ==================== prep kernel ====================
__global__ void prep_kernel(
    const float* __restrict__ nf,
    const float* __restrict__ Wih_n, const float* __restrict__ Whh_n,
    const float* __restrict__ bih_n, const float* __restrict__ bhh_n,
    const float* __restrict__ Wih_g, const float* __restrict__ Whh_g,
    const float* __restrict__ bih_g, const float* __restrict__ bhh_g,
    const float* __restrict__ Ws1,
    float* __restrict__ out)
{
    long t = (long)blockIdx.x * blockDim.x + threadIdx.x;

    if (t < 262144) {   // g_WcN [q][kp][col][oct][g]
        int q = (int)(t >> 16), rem = (int)(t & 65535);
        int kp = rem >> 11, r2 = rem & 2047;
        int col = r2 >> 5, oct = (r2 >> 2) & 7, g = r2 & 3;
        int k = oct * 32 + kp, hc = q * 64 + col;
        float v;
        if (g == 0)      v = Wih_n[hc * 270 + 14 + k] + Whh_n[hc * 256 + k];
        else if (g == 1) v = Wih_n[(256 + hc) * 270 + 14 + k] + Whh_n[(256 + hc) * 256 + k];
        else if (g == 2) v = Wih_n[(512 + hc) * 270 + 14 + k];
        else             v = Whh_n[(512 + hc) * 256 + k];
        g_WcN[t] = v; return;
    }
    t -= 262144;
    if (t < 524288) {   // g_Wg2 [q][kp][col][oct][g]
        int q = (int)(t >> 17), rem = (int)(t & 131071);
        int kp = rem >> 11, r2 = rem & 2047;
        int col = r2 >> 5, oct = (r2 >> 2) & 7, g = r2 & 3;
        int m = oct >> 2, kq = oct & 3;
        int k = kq * 64 + kp, hc = q * 64 + col;
        float v = 0.f;
        if (g < 3) v = m ? Whh_g[(g * 256 + hc) * 256 + k]
                         : Wih_g[(g * 256 + hc) * 256 + k];
        g_Wg2[t] = v; return;
    }
    t -= 524288;
    if (t < 1024) {     // g_bv4
        int q = (int)(t >> 8), lc = (int)(t & 255);
        int g = lc & 3, col = lc >> 2, hc = q * 64 + col;
        float v;
        if (g == 0)      v = bih_n[hc] + bhh_n[hc];
        else if (g == 1) v = bih_n[256 + hc] + bhh_n[256 + hc];
        else if (g == 2) v = bih_n[512 + hc];
        else             v = bhh_n[512 + hc];
        g_bv4[t] = v; return;
    }
    t -= 1024;
    if (t < 1024) {     // g_bgi4
        int q = (int)(t >> 8), lc = (int)(t & 255);
        int g = lc & 3, col = lc >> 2, hc = q * 64 + col;
        g_bgi4[t] = (g < 3) ? bih_g[g * 256 + hc] : 0.f; return;
    }
    t -= 1024;
    if (t < 1024) {     // g_bgh4
        int q = (int)(t >> 8), lc = (int)(t & 255);
        int g = lc & 3, col = lc >> 2, hc = q * 64 + col;
        g_bgh4[t] = (g < 3) ? bhh_g[g * 256 + hc] : 0.f; return;
    }
    t -= 1024;
    if (t < 7168) {     // g_PQi4
        int q = (int)(t / 1792), rem = (int)(t % 1792);
        int f = rem >> 8, lc = rem & 255;
        int g = lc & 3, col = lc >> 2, hc = q * 64 + col;
        g_PQi4[t] = (g < 3) ? Wih_n[(g * 256 + hc) * 270 + f] : 0.f; return;
    }
    t -= 7168;
    if (t < 7168) {     // g_PQj4
        int q = (int)(t / 1792), rem = (int)(t % 1792);
        int f = rem >> 8, lc = rem & 255;
        int g = lc & 3, col = lc >> 2, hc = q * 64 + col;
        g_PQj4[t] = (g < 3) ? Wih_n[(g * 256 + hc) * 270 + 7 + f] : 0.f; return;
    }
    t -= 7168;
    if (t < 16384) {    // W1T [k][u]
        int k = (int)(t >> 6), u = (int)(t & 63);
        g_Ws1T[t] = Ws1[u * 256 + k]; return;
    }
    t -= 16384;
    if (t < BB * NN) {  // argmax one-hot
        const float* p = nf + t * FF;
        int best = 0;
        #pragma unroll
        for (int f = 0; f < FF; f++) if (p[f] > 0.5f) best = f;
        g_idx[t] = best; return;
    }
    t -= BB * NN;
    if (t < TT) {       // anti-diagonal placement
        int m = (int)t;
        int d = (int)((1.0 + sqrt(1.0 + 8.0 * (double)m)) * 0.5);
        while (d * (d - 1) / 2 > m) d--;
        while ((d + 1) * d / 2 <= m) d++;
        int rr = m - d * (d - 1) / 2;
        g_rd[m] = rr; g_cd[m] = rr + NN - d; return;
    }
    t -= TT;
    if (t < BB * NN * FF) { out[OUT_X + t] = nf[t]; return; }
    t -= BB * NN * FF;
    if (t < BB * NN * NN) { out[OUT_ADJ + t] = 0.f; return; }
    t -= BB * NN * NN;
    if (t < BB * NN) { out[OUT_BATCH + t] = (float)(t >> 5); return; }
}

// ==================== helpers ====================
__device__ __forceinline__ float fex2(float x) {
    float r; asm("ex2.approx.ftz.f32 %0, %1;" : "=f"(r) : "f"(x)); return r;
}
__device__ __forceinline__ float frcp(float x) {
    float r; asm("rcp.approx.ftz.f32 %0, %1;" : "=f"(r) : "f"(x)); return r;
}
__device__ __forceinline__ float sigm(float x) {
    return frcp(1.f + fex2(-1.4426950408889634f * x));
}
__device__ __forceinline__ float ftanh(float x) {
    return 1.f - 2.f * frcp(1.f + fex2(2.8853900817779268f * x));
}
__device__ __forceinline__ void ffma2(ull& d, ull a, ull b) {
    asm("fma.rn.f32x2 %0, %1, %2, %0;" : "+l"(d) : "l"(a), "l"(b));
}
__device__ __forceinline__ void fadd2(ull& d, ull a) {
    asm("add.rn.f32x2 %0, %0, %1;" : "+l"(d) : "l"(a));
}
__device__ __forceinline__ ull dup2(float w) {
    ull r;
    asm("mov.b64 %0, {%1, %1};" : "=l"(r) : "r"(__float_as_uint(w)));
    return r;
}
__device__ __forceinline__ float2 unpk(ull v) {
    float2 r;
    r.x = __uint_as_float((unsigned)(v & 0xffffffffu));
    r.y = __uint_as_float((unsigned)(v >> 32));
    return r;
}
__device__ __forceinline__ ull pk(float x, float y) {
    return ((ull)__float_as_uint(y) << 32) | (ull)__float_as_uint(x);
}
__device__ __forceinline__ void st_peer64(float* p, unsigned peer, ull bits) {
    unsigned la = (unsigned)__cvta_generic_to_shared(p);
    unsigned ra;
    asm volatile("mapa.shared::cluster.u32 %0, %1, %2;" : "=r"(ra) : "r"(la), "r"(peer));
    asm volatile("st.shared::cluster.b64 [%0], %1;" :: "r"(ra), "l"(bits) : "memory");
}
__device__ __forceinline__ void st_peer64a(unsigned laddr, unsigned peer, ull bits) {
    unsigned ra;
    asm volatile("mapa.shared::cluster.u32 %0, %1, %2;" : "=r"(ra) : "r"(laddr), "r"(peer));
    asm volatile("st.shared::cluster.b64 [%0], %1;" :: "r"(ra), "l"(bits) : "memory");
}
__device__ __forceinline__ void pf_l1(const float* p) {
    asm volatile("prefetch.global.L1 [%0];" :: "l"(p));
}
__device__ __forceinline__ void mbar_init(unsigned addr, unsigned cnt) {
    asm volatile("mbarrier.init.shared.b64 [%0], %1;" :: "r"(addr), "r"(cnt) : "memory");
}
__device__ __forceinline__ void mbar_arrive_cluster(unsigned laddr, unsigned rank) {
    unsigned ra;
    asm volatile("mapa.shared::cluster.u32 %0, %1, %2;" : "=r"(ra) : "r"(laddr), "r"(rank));
    asm volatile("mbarrier.arrive.release.cluster.shared::cluster.b64 _, [%0];"
                 :: "r"(ra) : "memory");
}
__device__ __forceinline__ void mbar_wait(unsigned addr, unsigned parity) {
    asm volatile(
        "{\n\t.reg .pred P1;\n\t"
        "WAIT_LOOP_%=:\n\t"
        "mbarrier.try_wait.parity.acquire.cluster.shared::cta.b64 P1, [%0], %1, 0x989680;\n\t"
        "@P1 bra.uni WAIT_DONE_%=;\n\t"
        "bra.uni WAIT_LOOP_%=;\n\t"
        "WAIT_DONE_%=:\n\t}"
        :: "r"(addr), "r"(parity) : "memory");
}
#define CLUSTER_SYNC() do { \
    asm volatile("barrier.cluster.arrive.aligned;" ::: "memory"); \
    asm volatile("barrier.cluster.wait.aligned;" ::: "memory"); } while (0)

#define EXCHANGE() do { \
    __syncthreads(); \
    unsigned mb_ = mbarB32 + (unsigned)((xstep & 1) * 8); \
    if (t < 4) mbar_arrive_cluster(mb_, (unsigned)t); \
    mbar_wait(mb_, (unsigned)((xstep >> 1) & 1)); \
    xstep++; \
} while (0)

// ---- gemm core: thread owns 4 gates of one col, one K-octant ----
__device__ __forceinline__ void gbody(const float4 w, const float* __restrict__ hk,
                                      ull acc[16])
{
    ulonglong2 h01 = *(const ulonglong2*)(hk);
    ulonglong2 h23 = *(const ulonglong2*)(hk + 4);
    ull wd;
    wd = dup2(w.x);
    ffma2(acc[0], wd, h01.x); ffma2(acc[1], wd, h01.y);
    ffma2(acc[2], wd, h23.x); ffma2(acc[3], wd, h23.y);
    wd = dup2(w.y);
    ffma2(acc[4], wd, h01.x); ffma2(acc[5], wd, h01.y);
    ffma2(acc[6], wd, h23.x); ffma2(acc[7], wd, h23.y);
    wd = dup2(w.z);
    ffma2(acc[8],  wd, h01.x); ffma2(acc[9],  wd, h01.y);
    ffma2(acc[10], wd, h23.x); ffma2(acc[11], wd, h23.y);
    wd = dup2(w.w);
    ffma2(acc[12], wd, h01.x); ffma2(acc[13], wd, h01.y);
    ffma2(acc[14], wd, h23.x); ffma2(acc[15], wd, h23.y);
}

// ---------------- smem layout (float offsets) ----------------
#define SO_W1L  0                           // 4096 (W1T local slice [c][u])
#define SO_HA   4096
#define SO_HB   (SO_HA + HBUF)              // 6176
#define SO_GA   (SO_HB + HBUF + 4)          // 8260
#define SO_GB   (SO_GA + HBUF)              // 10340
#define SO_PQI  (SO_GB + HBUF)              // 12420
#define SO_PQJ  (SO_PQI + 1792)             // 14212
#define SO_PB   (SO_PQJ + 1792)             // 16004
#define SO_IDX  (SO_PB + 2048)              // 18052
#define SO_MBAR (SO_IDX + 256)              // 18308
#define SMEM_FLOATS (SO_MBAR + 4)           // 18312
#define SMEM_BYTES (SMEM_FLOATS * 4)        // 73248

// ==================== main chain kernel ====================
__global__ void __launch_bounds__(NT, 1) __cluster_dims__(4, 1, 1)
chain_kernel(const float* __restrict__ z, const float* __restrict__ uin,
             const float* __restrict__ bs1, const float* __restrict__ Ws2,
             const float* __restrict__ bs2, float* __restrict__ out)
{
    extern __shared__ float sm[];
    float* sW1L = sm + SO_W1L;
    float* hBuf[2] = { sm + SO_HA, sm + SO_HB };
    float* gBuf[2] = { sm + SO_GA, sm + SO_GB };
    float* sPQi = sm + SO_PQI;
    float* sPQj = sm + SO_PQJ;
    float* sPB  = sm + SO_PB;
    int*   sidx = (int*)(sm + SO_IDX);

    const int t = threadIdx.x;
    const int q = blockIdx.x & 3;
    const int cid = blockIdx.x >> 2;
    const int b0 = cid * RR;
    const unsigned sb32 = (unsigned)__cvta_generic_to_shared(sm);
    const unsigned mbarB32 = sb32 + SO_MBAR * 4;

    const float* WcG = g_WcN + q * 65536;
    const float* WgG = g_Wg2 + q * 131072;

    // ---- init smem ----
    for (int x = t; x < 4096; x += NT) sW1L[x] = g_Ws1T[q * 4096 + x];
    for (int x = t; x < FF * 256; x += NT) {
        sPQi[x] = g_PQi4[q * FF * 256 + x];
        sPQj[x] = g_PQj4[q * FF * 256 + x];
    }
    for (int x = t; x < 2048; x += NT) {      // graph h init (padded layout)
        int k = x >> 3, r = x & 7;
        gBuf[0][(k >> 5) * HPAD + (k & 31) * 8 + r] = z[(b0 + r) * HH + k];
    }
    if (t < 256) sidx[t] = g_idx[b0 * NN + t];
    if (t == 0) {
        mbar_init(mbarB32, 4);
        mbar_init(mbarB32 + 8, 4);
    }

    // roles
    const int col = t >> 3;            // 0..63
    const int oct = t & 7;             // K-octant / final row
    const bool b2 = (oct & 4) != 0;
    const bool b1 = (oct & 2) != 0;
    const bool b0v = (oct & 1) != 0;
    const int hco = (q * 2 + (col >> 5)) * HPAD + (col & 31) * 8;  // h col base
    // score roles
    const int su = t & 63;
    const int rp = (t >> 6) & 3;
    const int chalf = t >> 8;
    // finalize constants (warp 0: units t, t+32)
    const float b1a = bs1[t & 31];
    const float b1b = bs1[(t & 31) + 32];
    const float w2a = Ws2[t & 31];
    const float w2b = Ws2[(t & 31) + 32];
    const float bs2v = *bs2;

    // per-thread bias registers
    float4 bv4  = *(const float4*)(g_bv4  + q * 256 + col * 4);
    float4 bgi4 = *(const float4*)(g_bgi4 + q * 256 + col * 4);
    float4 bgh4 = *(const float4*)(g_bgh4 + q * 256 + col * 4);
    const float bva[4]  = { bv4.x, bv4.y, bv4.z, bv4.w };
    const float bgia[3] = { bgi4.x, bgi4.y, bgi4.z };
    const float bgha[3] = { bgh4.x, bgh4.y, bgh4.z };

    __syncthreads();
    CLUSTER_SYNC();

    int pb = 0, gpb = 0;
    int xstep = 0;

    const float* WpN = WcG + col * 32 + oct * 4;     // node weight column base
    const float* WpG = WgG + col * 32 + oct * 4;     // graph weight column base

    for (int i = 0; i < NN - 1; i++) {
        pb = 0;
        {   // node_h := graph_h (full padded copy)
            const float* gs = gBuf[gpb];
            float* d = hBuf[0];
            for (int x = t; x < HBUF; x += NT) d[x] = gs[x];
        }
        __syncthreads();

        const int fiT = sidx[oct * NN + i];

        for (int j = i + 1; j < NN; j++) {
            float* hR = hBuf[pb];
            float* hW = hBuf[pb ^ 1];
            const int pbsel = xstep & 1;

            // ---- node gemm: 32 k of octant oct, 8-deep prefetch ----
            ull acc[16];
            #pragma unroll
            for (int x = 0; x < 16; x++) acc[x] = 0ull;
            {
                const float* hq = hR + oct * HPAD;
                float4 wb[8];
                #pragma unroll
                for (int x = 0; x < 8; x++) wb[x] = *(const float4*)(WpN + x * 2048);
                #pragma unroll
                for (int blk = 0; blk < 4; blk++) {
                    float4 wc[8];
                    #pragma unroll
                    for (int x = 0; x < 8; x++) wc[x] = wb[x];
                    if (blk + 1 < 4) {
                        const float* np = WpN + (blk + 1) * 8 * 2048;
                        #pragma unroll
                        for (int x = 0; x < 8; x++) wb[x] = *(const float4*)(np + x * 2048);
                    }
                    const float* hkb = hq + blk * 64;
                    #pragma unroll
                    for (int x = 0; x < 8; x++) gbody(wc[x], hkb + x * 8, acc);
                }
            }

            // ---- butterfly reduce-scatter over octants ----
            ull k8[8];
            #pragma unroll
            for (int g = 0; g < 4; g++) {
                #pragma unroll
                for (int pkx = 0; pkx < 2; pkx++) {
                    ull keep = b2 ? acc[g * 4 + 2 + pkx] : acc[g * 4 + pkx];
                    ull send = b2 ? acc[g * 4 + pkx]     : acc[g * 4 + 2 + pkx];
                    ull r = __shfl_xor_sync(0xffffffffu, send, 4);
                    fadd2(keep, r);
                    k8[g * 2 + pkx] = keep;
                }
            }
            ull k4[4];
            #pragma unroll
            for (int g = 0; g < 4; g++) {
                ull keep = b1 ? k8[g * 2 + 1] : k8[g * 2];
                ull send = b1 ? k8[g * 2]     : k8[g * 2 + 1];
                ull r = __shfl_xor_sync(0xffffffffu, send, 2);
                fadd2(keep, r);
                k4[g] = keep;
            }
            #pragma unroll
            for (int g = 0; g < 4; g++) {
                ull r = __shfl_xor_sync(0xffffffffu, k4[g], 1);
                fadd2(k4[g], r);
            }

            // ---- in-register GRU activation (row = oct) ----
            {
                float vg[4];
                #pragma unroll
                for (int g = 0; g < 4; g++) {
                    float2 f = unpk(k4[g]);
                    vg[g] = (b0v ? f.y : f.x) + bva[g];
                }
                const int fj = sidx[oct * NN + j];
                float4 pi = *(const float4*)(sPQi + fiT * 256 + col * 4);
                float4 pj = *(const float4*)(sPQj + fj * 256 + col * 4);
                vg[0] += pi.x + pj.x;
                vg[1] += pi.y + pj.y;
                vg[2] += pi.z + pj.z;
                float ho = hR[hco + oct];
                float gr = sigm(vg[0]);
                float gz = sigm(vg[1]);
                float gn = ftanh(vg[2] + gr * vg[3]);
                float hn = (1.f - gz) * gn + gz * ho;
                float hpeer = __shfl_xor_sync(0xffffffffu, hn, 1);
                if (!b0v) {
                    ull bits = pk(hn, hpeer);
                    float* dp = hW + hco + oct;
                    *(ull*)dp = bits;
                    #pragma unroll
                    for (int pr = 0; pr < 4; pr++)
                        if (pr != q) st_peer64(dp, (unsigned)pr, bits);
                }
            }
            __syncthreads();   // local h slice complete

            // ---- packed score partials over own 64 cols ----
            {
                ull sacc = 0ull;
                const float* wp = sW1L + chalf * 32 * 64 + su;
                const float* hp = hW + (q * 2 + chalf) * HPAD + 2 * rp;
                #pragma unroll 8
                for (int c = 0; c < 32; c++)
                    ffma2(sacc, dup2(wp[c * 64]), *(const ull*)(hp + c * 8));
                unsigned laddr = sb32 +
                    (unsigned)((SO_PB + pbsel * 1024 + chalf * 512 + q * 128 + su * 2) * 4);
                st_peer64a(laddr, (unsigned)rp, sacc);
            }

            // warm L1 with next gemm's first weight block (no registers held)
            {
                const float* pfb = (j < NN - 1) ? WpN : WpG;
                #pragma unroll
                for (int x = 0; x < 8; x++) pf_l1(pfb + x * 2048);
            }
            EXCHANGE();

            // ---- finalize score + edges, single warp (t < 32) ----
            if (t < 32) {
                ull sa = 0ull, sb = 0ull;
                const ull* pbp = (const ull*)(sPB + pbsel * 1024);
                #pragma unroll
                for (int x = 0; x < 8; x++) {
                    fadd2(sa, pbp[x * 64 + t]);
                    fadd2(sb, pbp[x * 64 + 32 + t]);
                }
                float2 s0 = unpk(sa), s1 = unpk(sb);
                float r0 = fmaxf(s0.x + b1a, 0.f) * w2a + fmaxf(s1.x + b1b, 0.f) * w2b;
                float r1 = fmaxf(s0.y + b1a, 0.f) * w2a + fmaxf(s1.y + b1b, 0.f) * w2b;
                ull sc = pk(r0, r1);
                #pragma unroll
                for (int o = 16; o; o >>= 1) {
                    ull other = __shfl_down_sync(0xffffffffu, sc, o);
                    fadd2(sc, other);
                }
                if (t == 0) {
                    float2 v = unpk(sc);
                    int m = i * (NN - 1) - (i * (i - 1)) / 2 + (j - i - 1);
                    int rr = g_rd[m], cc = g_cd[m];
                    #pragma unroll
                    for (int s = 0; s < 2; s++) {
                        float prob = sigm((s ? v.y : v.x) + bs2v);
                        int b = b0 + 2 * q + s;
                        float uu = uin[b * TT + m];
                        float pc = fminf(fmaxf(prob, EPSF), 1.f - EPSF);
                        float e;
                        if (pc < 0.499f || pc > 0.501f) {
                            e = (log1pf(-pc + uu * (2.f * pc - 1.f)) - log1pf(-pc))
                              / (logf(pc) - log1pf(-pc));
                        } else {
                            e = uu;
                        }
                        float* adj = out + OUT_ADJ + b * (NN * NN);
                        adj[rr * NN + cc] = e;
                        adj[cc * NN + rr] = e;
                    }
                }
            }
            pb ^= 1;
        }

        // ---- graph GRU: octs 0-3 = Wgi quarters, 4-7 = Wgh quarters ----
        if (i < NN - 2) {
            const float* hfin = hBuf[pb];
            const float* ghR = gBuf[gpb];
            float* ghW = gBuf[gpb ^ 1];

            ull acc[16];
            #pragma unroll
            for (int x = 0; x < 16; x++) acc[x] = 0ull;
            {
                const float* hgb = (b2 ? ghR : hfin) + (oct & 3) * (2 * HPAD);
                float4 wb[8];
                #pragma unroll
                for (int x = 0; x < 8; x++) wb[x] = *(const float4*)(WpG + x * 2048);
                #pragma unroll
                for (int blk = 0; blk < 8; blk++) {
                    float4 wc[8];
                    #pragma unroll
                    for (int x = 0; x < 8; x++) wc[x] = wb[x];
                    if (blk + 1 < 8) {
                        const float* np = WpG + (blk + 1) * 8 * 2048;
                        #pragma unroll
                        for (int x = 0; x < 8; x++) wb[x] = *(const float4*)(np + x * 2048);
                    }
                    const float* hkb = hgb + ((blk & 4) ? (HPAD - 256) : 0) + blk * 64;
                    #pragma unroll
                    for (int x = 0; x < 8; x++) gbody(wc[x], hkb + x * 8, acc);
                }
            }

            // butterfly: xor2 (b1), xor1 (b0), xor4 (vi<->vh)
            ull k8g[8];
            #pragma unroll
            for (int g = 0; g < 4; g++) {
                #pragma unroll
                for (int pkx = 0; pkx < 2; pkx++) {
                    ull keep = b1 ? acc[g * 4 + 2 + pkx] : acc[g * 4 + pkx];
                    ull send = b1 ? acc[g * 4 + pkx]     : acc[g * 4 + 2 + pkx];
                    ull r = __shfl_xor_sync(0xffffffffu, send, 2);
                    fadd2(keep, r);
                    k8g[g * 2 + pkx] = keep;
                }
            }
            ull k4g[4];
            #pragma unroll
            for (int g = 0; g < 4; g++) {
                ull keep = b0v ? k8g[g * 2 + 1] : k8g[g * 2];
                ull send = b0v ? k8g[g * 2]     : k8g[g * 2 + 1];
                ull r = __shfl_xor_sync(0xffffffffu, send, 1);
                fadd2(keep, r);
                k4g[g] = keep;
            }
            {
                const int row = (b1 ? 4 : 0) + (b0v ? 2 : 0) + (b2 ? 1 : 0);
                float vi[3], vh[3];
                #pragma unroll
                for (int g = 0; g < 3; g++) {
                    ull other = __shfl_xor_sync(0xffffffffu, k4g[g], 4);
                    ull iu = b2 ? other : k4g[g];
                    ull hu = b2 ? k4g[g] : other;
                    float2 fi_ = unpk(iu), fh_ = unpk(hu);
                    vi[g] = (b2 ? fi_.y : fi_.x) + bgia[g];
                    vh[g] = (b2 ? fh_.y : fh_.x) + bgha[g];
                }
                float go = ghR[hco + row];
                float rr = sigm(vi[0] + vh[0]);
                float zz = sigm(vi[1] + vh[1]);
                float nn = ftanh(vi[2] + rr * vh[2]);
                float hn = (1.f - zz) * nn + zz * go;
                float hpeer = __shfl_xor_sync(0xffffffffu, hn, 4);
                if (!b2) {   // row even
                    ull bits = pk(hn, hpeer);
                    float* dp = ghW + hco + row;
                    *(ull*)dp = bits;
                    #pragma unroll
                    for (int pr = 0; pr < 4; pr++)
                        if (pr != q) st_peer64(dp, (unsigned)pr, bits);
                }
            }
            // warm L1 with next i's node weight block 0
            #pragma unroll
            for (int x = 0; x < 8; x++) pf_l1(WpN + x * 2048);
            EXCHANGE();
            gpb ^= 1;
        }
    }
    CLUSTER_SYNC();
}

// ==================== launch ====================
extern "C" void kernel_launch(void* const* d_in, const int* in_sizes, int n_in,
                              void* d_out, int out_size)
{
    const float* z     = (const float*)d_in[0];
    const float* nf    = (const float*)d_in[1];
    const float* u     = (const float*)d_in[2];
    const float* Wih_n = (const float*)d_in[3];
    const float* Whh_n = (const float*)d_in[4];
    const float* bih_n = (const float*)d_in[5];
    const float* bhh_n = (const float*)d_in[6];
    const float* Wih_g = (const float*)d_in[7];
    const float* Whh_g = (const float*)d_in[8];
    const float* bih_g = (const float*)d_in[9];
    const float* bhh_g = (const float*)d_in[10];
    const float* Ws1   = (const float*)d_in[11];
    const float* bs1   = (const float*)d_in[12];
    const float* Ws2   = (const float*)d_in[13];
    const float* bs2   = (const float*)d_in[14];
    float* out = (float*)d_out;

    const long total = 262144L + 524288L + 1024 * 3 + 7168 * 2 + 16384
                     + BB * NN + TT + BB * NN * FF + BB * NN * NN + BB * NN;
    int blocks = (int)((total + 255) / 256);
    prep_kernel<<<blocks, 256>>>(nf, Wih_n, Whh_n, bih_n, bhh_n,
                                 Wih_g, Whh_g, bih_g, bhh_g, Ws1, out);

    cudaFuncSetAttribute(chain_kernel,
                         cudaFuncAttributeMaxDynamicSharedMemorySize, SMEM_BYTES);
    chain_kernel<<<NCTA, NT, SMEM_BYTES>>>(z, u, bs1, Ws2, bs2, out);
}

// round 17
// speedup vs baseline: 1.0396x; 1.0396x over previous
#include <cuda_runtime.h>
#include <math.h>

// ---------------- problem constants ----------------
#define BB 256
#define NN 32
#define HH 256
#define FF 7
#define TT 496
#define RR 8                 // batch rows per 4-CTA cluster
#define NCLUST (BB / RR)
#define NCTA (NCLUST * 4)    // 128 CTAs
#define NT 512
#define HPAD 260             // floats per 32-k block of h (256 + 4 pad)
#define HBUF (8 * HPAD)      // 2080 floats per h buffer
#define EPSF 1.1920929e-07f

typedef unsigned long long ull;

// ---------------- device scratch ----------------
// node weights: [q][kp(32)][col(64)][oct(8)][gate(4)]  (k = oct*32 + kp)
__device__ float g_WcN[4 * 32 * 64 * 8 * 4];
// graph weights combined: [q][kp(64)][col(64)][oct(8)][gate(4)]
//   oct: m = oct>>2 (0=Wih_g, 1=Whh_g), kq = oct&3, k = kq*64 + kp; gate3 = 0
__device__ float g_Wg2[4 * 64 * 64 * 8 * 4];
__device__ float g_bv4[4 * 256];         // node combined bias [q][col*4+g]
__device__ float g_bgi4[4 * 256];
__device__ float g_bgh4[4 * 256];
__device__ float g_PQi4[4 * FF * 256];   // one-hot gathers [q][f][col*4+g], g3=0
__device__ float g_PQj4[4 * FF * 256];
__device__ float g_Ws1T[HH * 64];        // Ws1 transposed [k][u]
__device__ int   g_idx[BB * NN];
__device__ int   g_rd[TT];
__device__ int   g_cd[TT];

// output layout (float32): [x 57344][adj 262144][batch 8192]
#define OUT_X 0
#define OUT_ADJ 57344
#define OUT_BATCH 319488

// ==================== prep kernel ====================
__global__ void prep_kernel(
    const float* __restrict__ nf,
    const float* __restrict__ Wih_n, const float* __restrict__ Whh_n,
    const float* __restrict__ bih_n, const float* __restrict__ bhh_n,
    const float* __restrict__ Wih_g, const float* __restrict__ Whh_g,
    const float* __restrict__ bih_g, const float* __restrict__ bhh_g,
    const float* __restrict__ Ws1,
    float* __restrict__ out)
{
    long t = (long)blockIdx.x * blockDim.x + threadIdx.x;

    if (t < 262144) {   // g_WcN [q][kp][col][oct][g]
        int q = (int)(t >> 16), rem = (int)(t & 65535);
        int kp = rem >> 11, r2 = rem & 2047;
        int col = r2 >> 5, oct = (r2 >> 2) & 7, g = r2 & 3;
        int k = oct * 32 + kp, hc = q * 64 + col;
        float v;
        if (g == 0)      v = Wih_n[hc * 270 + 14 + k] + Whh_n[hc * 256 + k];
        else if (g == 1) v = Wih_n[(256 + hc) * 270 + 14 + k] + Whh_n[(256 + hc) * 256 + k];
        else if (g == 2) v = Wih_n[(512 + hc) * 270 + 14 + k];
        else             v = Whh_n[(512 + hc) * 256 + k];
        g_WcN[t] = v; return;
    }
    t -= 262144;
    if (t < 524288) {   // g_Wg2 [q][kp][col][oct][g]
        int q = (int)(t >> 17), rem = (int)(t & 131071);
        int kp = rem >> 11, r2 = rem & 2047;
        int col = r2 >> 5, oct = (r2 >> 2) & 7, g = r2 & 3;
        int m = oct >> 2, kq = oct & 3;
        int k = kq * 64 + kp, hc = q * 64 + col;
        float v = 0.f;
        if (g < 3) v = m ? Whh_g[(g * 256 + hc) * 256 + k]
                         : Wih_g[(g * 256 + hc) * 256 + k];
        g_Wg2[t] = v; return;
    }
    t -= 524288;
    if (t < 1024) {     // g_bv4
        int q = (int)(t >> 8), lc = (int)(t & 255);
        int g = lc & 3, col = lc >> 2, hc = q * 64 + col;
        float v;
        if (g == 0)      v = bih_n[hc] + bhh_n[hc];
        else if (g == 1) v = bih_n[256 + hc] + bhh_n[256 + hc];
        else if (g == 2) v = bih_n[512 + hc];
        else             v = bhh_n[512 + hc];
        g_bv4[t] = v; return;
    }
    t -= 1024;
    if (t < 1024) {     // g_bgi4
        int q = (int)(t >> 8), lc = (int)(t & 255);
        int g = lc & 3, col = lc >> 2, hc = q * 64 + col;
        g_bgi4[t] = (g < 3) ? bih_g[g * 256 + hc] : 0.f; return;
    }
    t -= 1024;
    if (t < 1024) {     // g_bgh4
        int q = (int)(t >> 8), lc = (int)(t & 255);
        int g = lc & 3, col = lc >> 2, hc = q * 64 + col;
        g_bgh4[t] = (g < 3) ? bhh_g[g * 256 + hc] : 0.f; return;
    }
    t -= 1024;
    if (t < 7168) {     // g_PQi4
        int q = (int)(t / 1792), rem = (int)(t % 1792);
        int f = rem >> 8, lc = rem & 255;
        int g = lc & 3, col = lc >> 2, hc = q * 64 + col;
        g_PQi4[t] = (g < 3) ? Wih_n[(g * 256 + hc) * 270 + f] : 0.f; return;
    }
    t -= 7168;
    if (t < 7168) {     // g_PQj4
        int q = (int)(t / 1792), rem = (int)(t % 1792);
        int f = rem >> 8, lc = rem & 255;
        int g = lc & 3, col = lc >> 2, hc = q * 64 + col;
        g_PQj4[t] = (g < 3) ? Wih_n[(g * 256 + hc) * 270 + 7 + f] : 0.f; return;
    }
    t -= 7168;
    if (t < 16384) {    // W1T [k][u]
        int k = (int)(t >> 6), u = (int)(t & 63);
        g_Ws1T[t] = Ws1[u * 256 + k]; return;
    }
    t -= 16384;
    if (t < BB * NN) {  // argmax one-hot
        const float* p = nf + t * FF;
        int best = 0;
        #pragma unroll
        for (int f = 0; f < FF; f++) if (p[f] > 0.5f) best = f;
        g_idx[t] = best; return;
    }
    t -= BB * NN;
    if (t < TT) {       // anti-diagonal placement
        int m = (int)t;
        int d = (int)((1.0 + sqrt(1.0 + 8.0 * (double)m)) * 0.5);
        while (d * (d - 1) / 2 > m) d--;
        while ((d + 1) * d / 2 <= m) d++;
        int rr = m - d * (d - 1) / 2;
        g_rd[m] = rr; g_cd[m] = rr + NN - d; return;
    }
    t -= TT;
    if (t < BB * NN * FF) { out[OUT_X + t] = nf[t]; return; }
    t -= BB * NN * FF;
    if (t < BB * NN * NN) { out[OUT_ADJ + t] = 0.f; return; }
    t -= BB * NN * NN;
    if (t < BB * NN) { out[OUT_BATCH + t] = (float)(t >> 5); return; }
}

// ==================== helpers ====================
__device__ __forceinline__ float fex2(float x) {
    float r; asm("ex2.approx.ftz.f32 %0, %1;" : "=f"(r) : "f"(x)); return r;
}
__device__ __forceinline__ float frcp(float x) {
    float r; asm("rcp.approx.ftz.f32 %0, %1;" : "=f"(r) : "f"(x)); return r;
}
__device__ __forceinline__ float sigm(float x) {
    return frcp(1.f + fex2(-1.4426950408889634f * x));
}
__device__ __forceinline__ float ftanh(float x) {
    return 1.f - 2.f * frcp(1.f + fex2(2.8853900817779268f * x));
}
__device__ __forceinline__ void ffma2(ull& d, ull a, ull b) {
    asm("fma.rn.f32x2 %0, %1, %2, %0;" : "+l"(d) : "l"(a), "l"(b));
}
__device__ __forceinline__ void fadd2(ull& d, ull a) {
    asm("add.rn.f32x2 %0, %0, %1;" : "+l"(d) : "l"(a));
}
__device__ __forceinline__ ull dup2(float w) {
    ull r;
    asm("mov.b64 %0, {%1, %1};" : "=l"(r) : "r"(__float_as_uint(w)));
    return r;
}
__device__ __forceinline__ float2 unpk(ull v) {
    float2 r;
    r.x = __uint_as_float((unsigned)(v & 0xffffffffu));
    r.y = __uint_as_float((unsigned)(v >> 32));
    return r;
}
__device__ __forceinline__ ull pk(float x, float y) {
    return ((ull)__float_as_uint(y) << 32) | (ull)__float_as_uint(x);
}
__device__ __forceinline__ void st_peer64(float* p, unsigned peer, ull bits) {
    unsigned la = (unsigned)__cvta_generic_to_shared(p);
    unsigned ra;
    asm volatile("mapa.shared::cluster.u32 %0, %1, %2;" : "=r"(ra) : "r"(la), "r"(peer));
    asm volatile("st.shared::cluster.b64 [%0], %1;" :: "r"(ra), "l"(bits) : "memory");
}
__device__ __forceinline__ void st_peer64a(unsigned laddr, unsigned peer, ull bits) {
    unsigned ra;
    asm volatile("mapa.shared::cluster.u32 %0, %1, %2;" : "=r"(ra) : "r"(laddr), "r"(peer));
    asm volatile("st.shared::cluster.b64 [%0], %1;" :: "r"(ra), "l"(bits) : "memory");
}
__device__ __forceinline__ void mbar_init(unsigned addr, unsigned cnt) {
    asm volatile("mbarrier.init.shared.b64 [%0], %1;" :: "r"(addr), "r"(cnt) : "memory");
}
__device__ __forceinline__ void mbar_arrive_cluster(unsigned laddr, unsigned rank) {
    unsigned ra;
    asm volatile("mapa.shared::cluster.u32 %0, %1, %2;" : "=r"(ra) : "r"(laddr), "r"(rank));
    asm volatile("mbarrier.arrive.release.cluster.shared::cluster.b64 _, [%0];"
                 :: "r"(ra) : "memory");
}
__device__ __forceinline__ void mbar_wait(unsigned addr, unsigned parity) {
    asm volatile(
        "{\n\t.reg .pred P1;\n\t"
        "WAIT_LOOP_%=:\n\t"
        "mbarrier.try_wait.parity.acquire.cluster.shared::cta.b64 P1, [%0], %1, 0x989680;\n\t"
        "@P1 bra.uni WAIT_DONE_%=;\n\t"
        "bra.uni WAIT_LOOP_%=;\n\t"
        "WAIT_DONE_%=:\n\t}"
        :: "r"(addr), "r"(parity) : "memory");
}
#define CLUSTER_SYNC() do { \
    asm volatile("barrier.cluster.arrive.aligned;" ::: "memory"); \
    asm volatile("barrier.cluster.wait.aligned;" ::: "memory"); } while (0)

#define EXCHANGE() do { \
    __syncthreads(); \
    unsigned mb_ = mbarB32 + (unsigned)((xstep & 1) * 8); \
    if (t < 4) mbar_arrive_cluster(mb_, (unsigned)t); \
    mbar_wait(mb_, (unsigned)((xstep >> 1) & 1)); \
    xstep++; \
} while (0)

// ---- gemm core: thread owns 4 gates of one col, one K-octant ----
__device__ __forceinline__ void gbody(const float4 w, const float* __restrict__ hk,
                                      ull acc[16])
{
    ulonglong2 h01 = *(const ulonglong2*)(hk);
    ulonglong2 h23 = *(const ulonglong2*)(hk + 4);
    ull wd;
    wd = dup2(w.x);
    ffma2(acc[0], wd, h01.x); ffma2(acc[1], wd, h01.y);
    ffma2(acc[2], wd, h23.x); ffma2(acc[3], wd, h23.y);
    wd = dup2(w.y);
    ffma2(acc[4], wd, h01.x); ffma2(acc[5], wd, h01.y);
    ffma2(acc[6], wd, h23.x); ffma2(acc[7], wd, h23.y);
    wd = dup2(w.z);
    ffma2(acc[8],  wd, h01.x); ffma2(acc[9],  wd, h01.y);
    ffma2(acc[10], wd, h23.x); ffma2(acc[11], wd, h23.y);
    wd = dup2(w.w);
    ffma2(acc[12], wd, h01.x); ffma2(acc[13], wd, h01.y);
    ffma2(acc[14], wd, h23.x); ffma2(acc[15], wd, h23.y);
}

// ---------------- smem layout (float offsets) ----------------
#define SO_W1L  0                           // 4096 (W1T local slice [c][u])
#define SO_HA   4096
#define SO_HB   (SO_HA + HBUF)              // 6176
#define SO_GA   (SO_HB + HBUF + 4)          // 8260
#define SO_GB   (SO_GA + HBUF)              // 10340
#define SO_PQI  (SO_GB + HBUF)              // 12420
#define SO_PQJ  (SO_PQI + 1792)             // 14212
#define SO_PB   (SO_PQJ + 1792)             // 16004
#define SO_IDX  (SO_PB + 2048)              // 18052
#define SO_MBAR (SO_IDX + 256)              // 18308
#define SMEM_FLOATS (SO_MBAR + 4)           // 18312
#define SMEM_BYTES (SMEM_FLOATS * 4)        // 73248

// ==================== main chain kernel ====================
__global__ void __launch_bounds__(NT, 1) __cluster_dims__(4, 1, 1)
chain_kernel(const float* __restrict__ z, const float* __restrict__ uin,
             const float* __restrict__ bs1, const float* __restrict__ Ws2,
             const float* __restrict__ bs2, float* __restrict__ out)
{
    extern __shared__ float sm[];
    float* sW1L = sm + SO_W1L;
    float* hBuf[2] = { sm + SO_HA, sm + SO_HB };
    float* gBuf[2] = { sm + SO_GA, sm + SO_GB };
    float* sPQi = sm + SO_PQI;
    float* sPQj = sm + SO_PQJ;
    float* sPB  = sm + SO_PB;
    int*   sidx = (int*)(sm + SO_IDX);

    const int t = threadIdx.x;
    const int q = blockIdx.x & 3;
    const int cid = blockIdx.x >> 2;
    const int b0 = cid * RR;
    const unsigned sb32 = (unsigned)__cvta_generic_to_shared(sm);
    const unsigned mbarB32 = sb32 + SO_MBAR * 4;

    const float* WcG = g_WcN + q * 65536;
    const float* WgG = g_Wg2 + q * 131072;

    // ---- init smem ----
    for (int x = t; x < 4096; x += NT) sW1L[x] = g_Ws1T[q * 4096 + x];
    for (int x = t; x < FF * 256; x += NT) {
        sPQi[x] = g_PQi4[q * FF * 256 + x];
        sPQj[x] = g_PQj4[q * FF * 256 + x];
    }
    for (int x = t; x < 2048; x += NT) {      // graph h init (padded layout)
        int k = x >> 3, r = x & 7;
        gBuf[0][(k >> 5) * HPAD + (k & 31) * 8 + r] = z[(b0 + r) * HH + k];
    }
    if (t < 256) sidx[t] = g_idx[b0 * NN + t];
    if (t == 0) {
        mbar_init(mbarB32, 4);
        mbar_init(mbarB32 + 8, 4);
    }

    // roles
    const int col = t >> 3;            // 0..63
    const int oct = t & 7;             // K-octant / final row
    const bool b2 = (oct & 4) != 0;
    const bool b1 = (oct & 2) != 0;
    const bool b0v = (oct & 1) != 0;
    const int hco = (q * 2 + (col >> 5)) * HPAD + (col & 31) * 8;  // h col base
    // score roles
    const int su = t & 63;
    const int rp = (t >> 6) & 3;
    const int chalf = t >> 8;
    // finalize constants (warp 0: units t, t+32)
    const float b1a = bs1[t & 31];
    const float b1b = bs1[(t & 31) + 32];
    const float w2a = Ws2[t & 31];
    const float w2b = Ws2[(t & 31) + 32];
    const float bs2v = *bs2;

    // per-thread bias registers
    float4 bv4  = *(const float4*)(g_bv4  + q * 256 + col * 4);
    float4 bgi4 = *(const float4*)(g_bgi4 + q * 256 + col * 4);
    float4 bgh4 = *(const float4*)(g_bgh4 + q * 256 + col * 4);
    const float bva[4]  = { bv4.x, bv4.y, bv4.z, bv4.w };
    const float bgia[3] = { bgi4.x, bgi4.y, bgi4.z };
    const float bgha[3] = { bgh4.x, bgh4.y, bgh4.z };

    __syncthreads();
    CLUSTER_SYNC();

    int pb = 0, gpb = 0;
    int xstep = 0;

    const float* WpN = WcG + col * 32 + oct * 4;     // node weight column base
    const float* WpG = WgG + col * 32 + oct * 4;     // graph weight column base

    for (int i = 0; i < NN - 1; i++) {
        pb = 0;
        {   // node_h := graph_h (full padded copy)
            const float* gs = gBuf[gpb];
            float* d = hBuf[0];
            for (int x = t; x < HBUF; x += NT) d[x] = gs[x];
        }
        __syncthreads();

        const int fiT = sidx[oct * NN + i];

        for (int j = i + 1; j < NN; j++) {
            float* hR = hBuf[pb];
            float* hW = hBuf[pb ^ 1];
            const int pbsel = xstep & 1;

            // ---- node gemm: 32 k of octant oct, 8-deep prefetch ----
            ull acc[16];
            #pragma unroll
            for (int x = 0; x < 16; x++) acc[x] = 0ull;
            {
                const float* hq = hR + oct * HPAD;
                float4 wb[8];
                #pragma unroll
                for (int x = 0; x < 8; x++) wb[x] = *(const float4*)(WpN + x * 2048);
                #pragma unroll
                for (int blk = 0; blk < 4; blk++) {
                    float4 wc[8];
                    #pragma unroll
                    for (int x = 0; x < 8; x++) wc[x] = wb[x];
                    if (blk + 1 < 4) {
                        const float* np = WpN + (blk + 1) * 8 * 2048;
                        #pragma unroll
                        for (int x = 0; x < 8; x++) wb[x] = *(const float4*)(np + x * 2048);
                    }
                    const float* hkb = hq + blk * 64;
                    #pragma unroll
                    for (int x = 0; x < 8; x++) gbody(wc[x], hkb + x * 8, acc);
                }
            }

            // ---- butterfly reduce-scatter over octants ----
            ull k8[8];
            #pragma unroll
            for (int g = 0; g < 4; g++) {
                #pragma unroll
                for (int pkx = 0; pkx < 2; pkx++) {
                    ull keep = b2 ? acc[g * 4 + 2 + pkx] : acc[g * 4 + pkx];
                    ull send = b2 ? acc[g * 4 + pkx]     : acc[g * 4 + 2 + pkx];
                    ull r = __shfl_xor_sync(0xffffffffu, send, 4);
                    fadd2(keep, r);
                    k8[g * 2 + pkx] = keep;
                }
            }
            ull k4[4];
            #pragma unroll
            for (int g = 0; g < 4; g++) {
                ull keep = b1 ? k8[g * 2 + 1] : k8[g * 2];
                ull send = b1 ? k8[g * 2]     : k8[g * 2 + 1];
                ull r = __shfl_xor_sync(0xffffffffu, send, 2);
                fadd2(keep, r);
                k4[g] = keep;
            }
            #pragma unroll
            for (int g = 0; g < 4; g++) {
                ull r = __shfl_xor_sync(0xffffffffu, k4[g], 1);
                fadd2(k4[g], r);
            }

            // ---- in-register GRU activation (row = oct) ----
            {
                float vg[4];
                #pragma unroll
                for (int g = 0; g < 4; g++) {
                    float2 f = unpk(k4[g]);
                    vg[g] = (b0v ? f.y : f.x) + bva[g];
                }
                const int fj = sidx[oct * NN + j];
                float4 pi = *(const float4*)(sPQi + fiT * 256 + col * 4);
                float4 pj = *(const float4*)(sPQj + fj * 256 + col * 4);
                vg[0] += pi.x + pj.x;
                vg[1] += pi.y + pj.y;
                vg[2] += pi.z + pj.z;
                float ho = hR[hco + oct];
                float gr = sigm(vg[0]);
                float gz = sigm(vg[1]);
                float gn = ftanh(vg[2] + gr * vg[3]);
                float hn = (1.f - gz) * gn + gz * ho;
                float hpeer = __shfl_xor_sync(0xffffffffu, hn, 1);
                if (!b0v) {
                    ull bits = pk(hn, hpeer);
                    float* dp = hW + hco + oct;
                    *(ull*)dp = bits;
                    #pragma unroll
                    for (int pr = 0; pr < 4; pr++)
                        if (pr != q) st_peer64(dp, (unsigned)pr, bits);
                }
            }
            __syncthreads();   // local h slice complete

            // ---- packed score partials over own 64 cols ----
            {
                ull sacc = 0ull;
                const float* wp = sW1L + chalf * 32 * 64 + su;
                const float* hp = hW + (q * 2 + chalf) * HPAD + 2 * rp;
                #pragma unroll 8
                for (int c = 0; c < 32; c++)
                    ffma2(sacc, dup2(wp[c * 64]), *(const ull*)(hp + c * 8));
                unsigned laddr = sb32 +
                    (unsigned)((SO_PB + pbsel * 1024 + chalf * 512 + q * 128 + su * 2) * 4);
                st_peer64a(laddr, (unsigned)rp, sacc);
            }
            EXCHANGE();

            // ---- finalize score + edges, single warp (t < 32) ----
            if (t < 32) {
                ull sa = 0ull, sb = 0ull;
                const ull* pbp = (const ull*)(sPB + pbsel * 1024);
                #pragma unroll
                for (int x = 0; x < 8; x++) {
                    fadd2(sa, pbp[x * 64 + t]);
                    fadd2(sb, pbp[x * 64 + 32 + t]);
                }
                float2 s0 = unpk(sa), s1 = unpk(sb);
                float r0 = fmaxf(s0.x + b1a, 0.f) * w2a + fmaxf(s1.x + b1b, 0.f) * w2b;
                float r1 = fmaxf(s0.y + b1a, 0.f) * w2a + fmaxf(s1.y + b1b, 0.f) * w2b;
                ull sc = pk(r0, r1);
                #pragma unroll
                for (int o = 16; o; o >>= 1) {
                    ull other = __shfl_down_sync(0xffffffffu, sc, o);
                    fadd2(sc, other);
                }
                if (t == 0) {
                    float2 v = unpk(sc);
                    int m = i * (NN - 1) - (i * (i - 1)) / 2 + (j - i - 1);
                    int rr = g_rd[m], cc = g_cd[m];
                    #pragma unroll
                    for (int s = 0; s < 2; s++) {
                        float prob = sigm((s ? v.y : v.x) + bs2v);
                        int b = b0 + 2 * q + s;
                        float uu = uin[b * TT + m];
                        float pc = fminf(fmaxf(prob, EPSF), 1.f - EPSF);
                        float e;
                        if (pc < 0.499f || pc > 0.501f) {
                            e = (log1pf(-pc + uu * (2.f * pc - 1.f)) - log1pf(-pc))
                              / (logf(pc) - log1pf(-pc));
                        } else {
                            e = uu;
                        }
                        float* adj = out + OUT_ADJ + b * (NN * NN);
                        adj[rr * NN + cc] = e;
                        adj[cc * NN + rr] = e;
                    }
                }
            }
            pb ^= 1;
        }

        // ---- graph GRU: octs 0-3 = Wgi quarters, 4-7 = Wgh quarters ----
        if (i < NN - 2) {
            const float* hfin = hBuf[pb];
            const float* ghR = gBuf[gpb];
            float* ghW = gBuf[gpb ^ 1];

            ull acc[16];
            #pragma unroll
            for (int x = 0; x < 16; x++) acc[x] = 0ull;
            {
                const float* hgb = (b2 ? ghR : hfin) + (oct & 3) * (2 * HPAD);
                float4 wb[8];
                #pragma unroll
                for (int x = 0; x < 8; x++) wb[x] = *(const float4*)(WpG + x * 2048);
                #pragma unroll
                for (int blk = 0; blk < 8; blk++) {
                    float4 wc[8];
                    #pragma unroll
                    for (int x = 0; x < 8; x++) wc[x] = wb[x];
                    if (blk + 1 < 8) {
                        const float* np = WpG + (blk + 1) * 8 * 2048;
                        #pragma unroll
                        for (int x = 0; x < 8; x++) wb[x] = *(const float4*)(np + x * 2048);
                    }
                    const float* hkb = hgb + ((blk & 4) ? (HPAD - 256) : 0) + blk * 64;
                    #pragma unroll
                    for (int x = 0; x < 8; x++) gbody(wc[x], hkb + x * 8, acc);
                }
            }

            // butterfly: xor2 (b1), xor1 (b0), xor4 (vi<->vh)
            ull k8g[8];
            #pragma unroll
            for (int g = 0; g < 4; g++) {
                #pragma unroll
                for (int pkx = 0; pkx < 2; pkx++) {
                    ull keep = b1 ? acc[g * 4 + 2 + pkx] : acc[g * 4 + pkx];
                    ull send = b1 ? acc[g * 4 + pkx]     : acc[g * 4 + 2 + pkx];
                    ull r = __shfl_xor_sync(0xffffffffu, send, 2);
                    fadd2(keep, r);
                    k8g[g * 2 + pkx] = keep;
                }
            }
            ull k4g[4];
            #pragma unroll
            for (int g = 0; g < 4; g++) {
                ull keep = b0v ? k8g[g * 2 + 1] : k8g[g * 2];
                ull send = b0v ? k8g[g * 2]     : k8g[g * 2 + 1];
                ull r = __shfl_xor_sync(0xffffffffu, send, 1);
                fadd2(keep, r);
                k4g[g] = keep;
            }
            {
                const int row = (b1 ? 4 : 0) + (b0v ? 2 : 0) + (b2 ? 1 : 0);
                float vi[3], vh[3];
                #pragma unroll
                for (int g = 0; g < 3; g++) {
                    ull other = __shfl_xor_sync(0xffffffffu, k4g[g], 4);
                    ull iu = b2 ? other : k4g[g];
                    ull hu = b2 ? k4g[g] : other;
                    float2 fi_ = unpk(iu), fh_ = unpk(hu);
                    vi[g] = (b2 ? fi_.y : fi_.x) + bgia[g];
                    vh[g] = (b2 ? fh_.y : fh_.x) + bgha[g];
                }
                float go = ghR[hco + row];
                float rr = sigm(vi[0] + vh[0]);
                float zz = sigm(vi[1] + vh[1]);
                float nn = ftanh(vi[2] + rr * vh[2]);
                float hn = (1.f - zz) * nn + zz * go;
                float hpeer = __shfl_xor_sync(0xffffffffu, hn, 4);
                if (!b2) {   // row even
                    ull bits = pk(hn, hpeer);
                    float* dp = ghW + hco + row;
                    *(ull*)dp = bits;
                    #pragma unroll
                    for (int pr = 0; pr < 4; pr++)
                        if (pr != q) st_peer64(dp, (unsigned)pr, bits);
                }
            }
            EXCHANGE();
            gpb ^= 1;
        }
    }
    CLUSTER_SYNC();
}

// ==================== launch ====================
extern "C" void kernel_launch(void* const* d_in, const int* in_sizes, int n_in,
                              void* d_out, int out_size)
{
    const float* z     = (const float*)d_in[0];
    const float* nf    = (const float*)d_in[1];
    const float* u     = (const float*)d_in[2];
    const float* Wih_n = (const float*)d_in[3];
    const float* Whh_n = (const float*)d_in[4];
    const float* bih_n = (const float*)d_in[5];
    const float* bhh_n = (const float*)d_in[6];
    const float* Wih_g = (const float*)d_in[7];
    const float* Whh_g = (const float*)d_in[8];
    const float* bih_g = (const float*)d_in[9];
    const float* bhh_g = (const float*)d_in[10];
    const float* Ws1   = (const float*)d_in[11];
    const float* bs1   = (const float*)d_in[12];
    const float* Ws2   = (const float*)d_in[13];
    const float* bs2   = (const float*)d_in[14];
    float* out = (float*)d_out;

    const long total = 262144L + 524288L + 1024 * 3 + 7168 * 2 + 16384
                     + BB * NN + TT + BB * NN * FF + BB * NN * NN + BB * NN;
    int blocks = (int)((total + 255) / 256);
    prep_kernel<<<blocks, 256>>>(nf, Wih_n, Whh_n, bih_n, bhh_n,
                                 Wih_g, Whh_g, bih_g, bhh_g, Ws1, out);

    cudaFuncSetAttribute(chain_kernel,
                         cudaFuncAttributeMaxDynamicSharedMemorySize, SMEM_BYTES);
    chain_kernel<<<NCTA, NT, SMEM_BYTES>>>(z, u, bs1, Ws2, bs2, out);
}